// round 2
// baseline (speedup 1.0000x reference)
#include <cuda_runtime.h>
#include <cstdint>

#define B_   16
#define T_   1024
#define DIN  4608
#define DRED 128
#define H_   32
#define G3   96          // 3*H
#define TAU  12
#define QPV  1e4f

// ---------------- scratch (no cudaMalloc allowed) ----------------
__device__ float g_wc[G3 * DIN];      // folded weight  w_ih @ w_dr   [96,4608]
__device__ float g_bc[G3];            // folded bias    b_ih + w_ih@b_dr
__device__ float g_gi[B_ * T_ * G3];  // input-gate preactivations
__device__ float g_hs[B_ * T_ * H_]; // GRU hidden states

__device__ __forceinline__ float sigmoid_fast(float x) {
    return __fdividef(1.f, 1.f + __expf(-x));
}
__device__ __forceinline__ float tanh_fast(float x) {
    // 2*sigmoid(2x)-1 : safe at both tails (no inf/inf)
    return 2.f * __fdividef(1.f, 1.f + __expf(-2.f * x)) - 1.f;
}

// ---------------- prep: fold the two linear layers ----------------
__global__ void prep_bc(const float* __restrict__ w_ih,
                        const float* __restrict__ b_dr,
                        const float* __restrict__ b_ih) {
    int o = threadIdx.x;              // 96 threads
    float acc = b_ih[o];
    #pragma unroll 8
    for (int r = 0; r < DRED; r++) acc = fmaf(w_ih[o * DRED + r], b_dr[r], acc);
    g_bc[o] = acc;
}

// w_c[o][d] = sum_r w_ih[o][r] * w_dr[r][d]   (96 x 4608, K=128)
// One block of 128 threads per 128 columns d; w_ih read via read-only cache.
__global__ void __launch_bounds__(128) prep_wc(const float* __restrict__ w_ih,
                                               const float* __restrict__ w_dr) {
    int tid = threadIdx.x;
    int d = blockIdx.x * 128 + tid;   // 36 blocks * 128 = 4608 columns
    float acc[G3];
    #pragma unroll
    for (int o = 0; o < G3; o++) acc[o] = 0.f;
    for (int r = 0; r < DRED; r++) {
        float a = w_dr[(size_t)r * DIN + d];
        #pragma unroll
        for (int o = 0; o < G3; o++)
            acc[o] = fmaf(__ldg(&w_ih[o * DRED + r]), a, acc[o]);
    }
    #pragma unroll
    for (int o = 0; o < G3; o++) g_wc[(size_t)o * DIN + d] = acc[o];
}

// ---------------- big GEMM: gi = x @ w_c.T + b_c ----------------
// M=16384, N=96, K=4608.  BM=128, BN=96, BK=32, 256 thr, 8x6 microtile.
#define BM 128
#define BN 96
#define BK 32

__global__ void __launch_bounds__(256) gemm_gi(const float* __restrict__ x) {
    __shared__ float As[BK][BM + 4];   // k-major, padded
    __shared__ float Bs[BK][BN + 4];
    int tid = threadIdx.x;
    int tx = tid & 15, ty = tid >> 4;
    int m0 = ty * 8, n0 = tx * 6;
    int mBase = blockIdx.x * BM;

    float acc[8][6];
    #pragma unroll
    for (int i = 0; i < 8; i++)
        #pragma unroll
        for (int j = 0; j < 6; j++) acc[i][j] = 0.f;

    for (int kb = 0; kb < DIN; kb += BK) {
        // A tile: 128x32, float4 loads, transpose into As[k][m]
        #pragma unroll
        for (int i = 0; i < 4; i++) {
            int idx = tid + i * 256;            // 0..1023
            int row = idx >> 3, kq = idx & 7;
            float4 v = *reinterpret_cast<const float4*>(
                x + (size_t)(mBase + row) * DIN + kb + kq * 4);
            As[kq * 4 + 0][row] = v.x; As[kq * 4 + 1][row] = v.y;
            As[kq * 4 + 2][row] = v.z; As[kq * 4 + 3][row] = v.w;
        }
        // B tile: 96x32 from g_wc
        #pragma unroll
        for (int i = 0; i < 3; i++) {
            int idx = tid + i * 256;            // 0..767
            int n = idx >> 3, kq = idx & 7;
            float4 v = *reinterpret_cast<const float4*>(
                g_wc + (size_t)n * DIN + kb + kq * 4);
            Bs[kq * 4 + 0][n] = v.x; Bs[kq * 4 + 1][n] = v.y;
            Bs[kq * 4 + 2][n] = v.z; Bs[kq * 4 + 3][n] = v.w;
        }
        __syncthreads();

        #pragma unroll 8
        for (int kk = 0; kk < BK; kk++) {
            float a[8], bb[6];
            float4 a0 = *reinterpret_cast<const float4*>(&As[kk][m0]);
            float4 a1 = *reinterpret_cast<const float4*>(&As[kk][m0 + 4]);
            a[0] = a0.x; a[1] = a0.y; a[2] = a0.z; a[3] = a0.w;
            a[4] = a1.x; a[5] = a1.y; a[6] = a1.z; a[7] = a1.w;
            float2 b0 = *reinterpret_cast<const float2*>(&Bs[kk][n0]);
            float2 b1 = *reinterpret_cast<const float2*>(&Bs[kk][n0 + 2]);
            float2 b2 = *reinterpret_cast<const float2*>(&Bs[kk][n0 + 4]);
            bb[0] = b0.x; bb[1] = b0.y; bb[2] = b1.x;
            bb[3] = b1.y; bb[4] = b2.x; bb[5] = b2.y;
            #pragma unroll
            for (int i = 0; i < 8; i++)
                #pragma unroll
                for (int j = 0; j < 6; j++)
                    acc[i][j] = fmaf(a[i], bb[j], acc[i][j]);
        }
        __syncthreads();
    }

    float bias[6];
    #pragma unroll
    for (int j = 0; j < 6; j++) bias[j] = g_bc[n0 + j];
    #pragma unroll
    for (int i = 0; i < 8; i++) {
        size_t base = (size_t)(mBase + m0 + i) * G3 + n0;
        #pragma unroll
        for (int j = 0; j < 6; j++) g_gi[base + j] = acc[i][j] + bias[j];
    }
}

// ---------------- GRU: one warp per batch element ----------------
__global__ void gru_kernel(const float* __restrict__ w_hh,
                           const float* __restrict__ b_hh) {
    int b = blockIdx.x, lane = threadIdx.x;
    float wr[32], wz[32], wn[32];
    #pragma unroll
    for (int j = 0; j < 32; j++) {
        wr[j] = w_hh[lane * 32 + j];
        wz[j] = w_hh[(32 + lane) * 32 + j];
        wn[j] = w_hh[(64 + lane) * 32 + j];
    }
    float bhr = b_hh[lane], bhz = b_hh[32 + lane], bhn = b_hh[64 + lane];
    const float* gib = g_gi + (size_t)b * T_ * G3;
    float* hsb = g_hs + (size_t)b * T_ * H_;

    float h = 0.f;
    // prefetch depth 2 (branch-free: clamp index, last 2 prefetches are dummies)
    float grA = gib[lane],        gzA = gib[32 + lane],      gnA = gib[64 + lane];
    float grB = gib[G3 + lane],   gzB = gib[G3 + 32 + lane], gnB = gib[G3 + 64 + lane];

    for (int t = 0; t < T_; t++) {
        int tp = (t + 2 < T_) ? (t + 2) : (T_ - 1);
        const float* p = gib + (size_t)tp * G3;
        float grC = p[lane], gzC = p[32 + lane], gnC = p[64 + lane];

        float ar = 0.f, az = 0.f, an = 0.f;
        #pragma unroll
        for (int j = 0; j < 32; j++) {
            float hj = __shfl_sync(0xffffffffu, h, j);
            ar = fmaf(wr[j], hj, ar);
            az = fmaf(wz[j], hj, az);
            an = fmaf(wn[j], hj, an);
        }
        float r = sigmoid_fast(grA + ar + bhr);
        float z = sigmoid_fast(gzA + az + bhz);
        float n = tanh_fast(gnA + r * (an + bhn));
        h = n + z * (h - n);             // (1-z)*n + z*h
        hsb[t * H_ + lane] = h;
        grA = grB; gzA = gzB; gnA = gnB;
        grB = grC; gzB = gzC; gnB = gnC;
    }
}

// ---------------- post: q, windows, masked mean, output head ----------------
__global__ void __launch_bounds__(128) post_kernel(
        const int* __restrict__ x_len,
        const float* __restrict__ w_reg, const float* __restrict__ b_reg,
        const float* __restrict__ wn1, const float* __restrict__ bn1,
        const float* __restrict__ wn2, const float* __restrict__ bn2,
        const float* __restrict__ wlm, const float* __restrict__ blm,
        float* __restrict__ out, int out_size) {
    __shared__ float sq[T_];
    __shared__ float red[128];
    __shared__ float swr[32];
    int b = blockIdx.x, tid = threadIdx.x;
    int len = x_len[b];
    if (tid < 32) swr[tid] = w_reg[tid];
    __syncthreads();
    float br = b_reg[0];
    const float* hsb = g_hs + (size_t)b * T_ * H_;

    for (int t = tid; t < T_; t += 128) {
        const float* hp = hsb + t * H_;
        float acc = 0.f;
        #pragma unroll
        for (int j = 0; j < 32; j++) acc = fmaf(hp[j], swr[j], acc);
        sq[t] = acc + br;
    }
    __syncthreads();

    float sum = 0.f;
    for (int t = tid; t < T_; t += 128) {
        if (t < len) {
            // l[t] = min(q[t-11 .. t])  (left pad +inf == skip i<0)
            float l = sq[t];
            #pragma unroll
            for (int k = 1; k < TAU; k++) {
                int i = t - k;
                if (i >= 0) l = fminf(l, sq[i]);
            }
            // exp-weighted forward window over q_eff (masked -> QP)
            float num = 0.f, den = 0.f;
            #pragma unroll
            for (int k = 0; k < TAU; k++) {
                int i = t + k;
                float v = (i < len) ? sq[i] : QPV;   // len<=T so i<len => in range
                float e = __expf(-v);
                num = fmaf(v, e, num);
                den += e;
            }
            float m = num / den;                      // (num/12)/(den/12)
            sum += 0.5f * m + 0.5f * l;
        }
    }
    red[tid] = sum;
    __syncthreads();
    for (int s = 64; s > 0; s >>= 1) {
        if (tid < s) red[tid] += red[tid + s];
        __syncthreads();
    }
    if (tid == 0) {
        float rel      = red[0] / (float)len;
        float relative = 1.f / (1.f + expf(-rel));
        float mapped   = wn2[0] * (1.f / (1.f + expf(-(relative * wn1[0] + bn1[0])))) + bn2[0];
        float aligned  = mapped * wlm[0] + blm[0];
        if (out_size >= 3 * B_) {
            out[b] = relative; out[B_ + b] = mapped; out[2 * B_ + b] = aligned;
        } else {
            out[b] = aligned;
        }
    }
}

// ---------------- launch ----------------
extern "C" void kernel_launch(void* const* d_in, const int* in_sizes, int n_in,
                              void* d_out, int out_size) {
    const float* x     = (const float*)d_in[0];
    const int*   xlen  = (const int*)  d_in[1];
    const float* w_dr  = (const float*)d_in[2];
    const float* b_dr  = (const float*)d_in[3];
    const float* w_ih  = (const float*)d_in[4];
    const float* w_hh  = (const float*)d_in[5];
    const float* b_ih  = (const float*)d_in[6];
    const float* b_hh  = (const float*)d_in[7];
    const float* w_reg = (const float*)d_in[8];
    const float* b_reg = (const float*)d_in[9];
    const float* wn1   = (const float*)d_in[10];
    const float* bn1   = (const float*)d_in[11];
    const float* wn2   = (const float*)d_in[12];
    const float* bn2   = (const float*)d_in[13];
    const float* wlm   = (const float*)d_in[14];
    const float* blm   = (const float*)d_in[15];

    prep_wc<<<DIN / 128, 128>>>(w_ih, w_dr);
    prep_bc<<<1, G3>>>(w_ih, b_dr, b_ih);
    gemm_gi<<<(B_ * T_) / BM, 256>>>(x);
    gru_kernel<<<B_, 32>>>(w_hh, b_hh);
    post_kernel<<<B_, 128>>>(xlen, w_reg, b_reg, wn1, bn1, wn2, bn2, wlm, blm,
                             (float*)d_out, out_size);
}

// round 4
// speedup vs baseline: 1.5133x; 1.5133x over previous
#include <cuda_runtime.h>
#include <cuda_bf16.h>
#include <cstdint>

#define B_   16
#define T_   1024
#define DIN  4608
#define DRED 128
#define H_   32
#define G3   96          // 3*H
#define TAU  12
#define QPV  1e4f

// ---------------- scratch (no cudaMalloc allowed) ----------------
__device__ __nv_bfloat16 g_wc_hi[G3 * DIN];  // folded weight, bf16 hi part
__device__ __nv_bfloat16 g_wc_lo[G3 * DIN];  // folded weight, bf16 lo part
__device__ float g_bc[G3];                   // folded bias b_ih + w_ih@b_dr
__device__ float g_gi[B_ * T_ * G3];         // input-gate preactivations
__device__ float g_hs[B_ * T_ * H_];         // GRU hidden states

__device__ __forceinline__ float sigmoid_fast(float x) {
    return __fdividef(1.f, 1.f + __expf(-x));
}
__device__ __forceinline__ float tanh_fast(float x) {
    return 2.f * __fdividef(1.f, 1.f + __expf(-2.f * x)) - 1.f;
}

// ---------------- prep: fold the two linear layers ----------------
__global__ void prep_bc(const float* __restrict__ w_ih,
                        const float* __restrict__ b_dr,
                        const float* __restrict__ b_ih) {
    int o = threadIdx.x;              // 96 threads
    float acc = b_ih[o];
    #pragma unroll 8
    for (int r = 0; r < DRED; r++) acc = fmaf(w_ih[o * DRED + r], b_dr[r], acc);
    g_bc[o] = acc;
}

// w_c[o][d] = sum_r w_ih[o][r] * w_dr[r][d]; split into bf16 hi/lo
__global__ void __launch_bounds__(128) prep_wc(const float* __restrict__ w_ih,
                                               const float* __restrict__ w_dr) {
    int tid = threadIdx.x;
    int d = blockIdx.x * 128 + tid;   // 36 blocks * 128 = 4608 columns
    float acc[G3];
    #pragma unroll
    for (int o = 0; o < G3; o++) acc[o] = 0.f;
    for (int r = 0; r < DRED; r++) {
        float a = w_dr[(size_t)r * DIN + d];
        #pragma unroll
        for (int o = 0; o < G3; o++)
            acc[o] = fmaf(__ldg(&w_ih[o * DRED + r]), a, acc[o]);
    }
    #pragma unroll
    for (int o = 0; o < G3; o++) {
        float v = acc[o];
        __nv_bfloat16 hi = __float2bfloat16(v);
        __nv_bfloat16 lo = __float2bfloat16(v - __bfloat162float(hi));
        g_wc_hi[(size_t)o * DIN + d] = hi;
        g_wc_lo[(size_t)o * DIN + d] = lo;
    }
}

// ---------------- big GEMM: gi = x @ w_c.T + b_c  (bf16x3 HMMA) ----------------
// M=16384, N=96, K=4608.  Block tile 128x96xBK32, 8 warps (4x2), warp 32x48.
#define GBM 128
#define GBN 96
#define GBK 32
#define APAD 40   // bf16 elems per smem row (80 B, conflict-spread)

__device__ __forceinline__ void mma_bf16(float c[4], const uint32_t a[4],
                                         uint32_t b0, uint32_t b1) {
    asm volatile(
        "mma.sync.aligned.m16n8k16.row.col.f32.bf16.bf16.f32 "
        "{%0,%1,%2,%3}, {%4,%5,%6,%7}, {%8,%9}, {%0,%1,%2,%3};\n"
        : "+f"(c[0]), "+f"(c[1]), "+f"(c[2]), "+f"(c[3])
        : "r"(a[0]), "r"(a[1]), "r"(a[2]), "r"(a[3]), "r"(b0), "r"(b1));
}

__global__ void __launch_bounds__(256) gemm_gi(const float* __restrict__ x) {
    __shared__ __nv_bfloat16 As_hi[GBM][APAD], As_lo[GBM][APAD];  // 20 KB
    __shared__ __nv_bfloat16 Bs_hi[GBN][APAD], Bs_lo[GBN][APAD];  // 15 KB
    int tid = threadIdx.x;
    int wid = tid >> 5, lane = tid & 31;
    int wm = wid & 3, wn = wid >> 2;          // 4 x 2 warp grid
    int g = lane >> 2, tq = lane & 3;         // fragment row-group / quad
    int mBase = blockIdx.x * GBM;

    float c[2][6][4];
    #pragma unroll
    for (int mt = 0; mt < 2; mt++)
        #pragma unroll
        for (int nt = 0; nt < 6; nt++)
            #pragma unroll
            for (int i = 0; i < 4; i++) c[mt][nt][i] = 0.f;

    for (int kb = 0; kb < DIN; kb += GBK) {
        // --- A tile: 128x32 fp32 -> bf16 hi/lo in smem ---
        #pragma unroll
        for (int i = 0; i < 4; i++) {
            int idx = tid + i * 256;           // 0..1023
            int row = idx >> 3, kq = idx & 7;  // cols 4kq..4kq+3
            float4 v = *reinterpret_cast<const float4*>(
                x + (size_t)(mBase + row) * DIN + kb + 4 * kq);
            __nv_bfloat16 h0 = __float2bfloat16(v.x);
            __nv_bfloat16 h1 = __float2bfloat16(v.y);
            __nv_bfloat16 h2 = __float2bfloat16(v.z);
            __nv_bfloat16 h3 = __float2bfloat16(v.w);
            __nv_bfloat16 l0 = __float2bfloat16(v.x - __bfloat162float(h0));
            __nv_bfloat16 l1 = __float2bfloat16(v.y - __bfloat162float(h1));
            __nv_bfloat16 l2 = __float2bfloat16(v.z - __bfloat162float(h2));
            __nv_bfloat16 l3 = __float2bfloat16(v.w - __bfloat162float(h3));
            *reinterpret_cast<__nv_bfloat162*>(&As_hi[row][4 * kq])     = {h0, h1};
            *reinterpret_cast<__nv_bfloat162*>(&As_hi[row][4 * kq + 2]) = {h2, h3};
            *reinterpret_cast<__nv_bfloat162*>(&As_lo[row][4 * kq])     = {l0, l1};
            *reinterpret_cast<__nv_bfloat162*>(&As_lo[row][4 * kq + 2]) = {l2, l3};
        }
        // --- B tile: 96x32 bf16 hi/lo ---
        #pragma unroll
        for (int i = 0; i < 6; i++) {
            int idx = tid + i * 256;            // 0..1535
            int n = idx >> 4, kq = idx & 15;    // bf16 cols 2kq..2kq+1
            *reinterpret_cast<__nv_bfloat162*>(&Bs_hi[n][2 * kq]) =
                *reinterpret_cast<const __nv_bfloat162*>(&g_wc_hi[(size_t)n * DIN + kb + 2 * kq]);
            *reinterpret_cast<__nv_bfloat162*>(&Bs_lo[n][2 * kq]) =
                *reinterpret_cast<const __nv_bfloat162*>(&g_wc_lo[(size_t)n * DIN + kb + 2 * kq]);
        }
        __syncthreads();

        #pragma unroll
        for (int ks = 0; ks < 2; ks++) {
            uint32_t ah[2][4], al[2][4];
            #pragma unroll
            for (int mt = 0; mt < 2; mt++) {
                int r = wm * 32 + mt * 16 + g;
                int cbase = ks * 16 + 2 * tq;
                ah[mt][0] = *reinterpret_cast<const uint32_t*>(&As_hi[r][cbase]);
                ah[mt][1] = *reinterpret_cast<const uint32_t*>(&As_hi[r + 8][cbase]);
                ah[mt][2] = *reinterpret_cast<const uint32_t*>(&As_hi[r][cbase + 8]);
                ah[mt][3] = *reinterpret_cast<const uint32_t*>(&As_hi[r + 8][cbase + 8]);
                al[mt][0] = *reinterpret_cast<const uint32_t*>(&As_lo[r][cbase]);
                al[mt][1] = *reinterpret_cast<const uint32_t*>(&As_lo[r + 8][cbase]);
                al[mt][2] = *reinterpret_cast<const uint32_t*>(&As_lo[r][cbase + 8]);
                al[mt][3] = *reinterpret_cast<const uint32_t*>(&As_lo[r + 8][cbase + 8]);
            }
            #pragma unroll
            for (int nt = 0; nt < 6; nt++) {
                int nr = wn * 48 + nt * 8 + g;
                int cbase = ks * 16 + 2 * tq;
                uint32_t bh0 = *reinterpret_cast<const uint32_t*>(&Bs_hi[nr][cbase]);
                uint32_t bh1 = *reinterpret_cast<const uint32_t*>(&Bs_hi[nr][cbase + 8]);
                uint32_t bl0 = *reinterpret_cast<const uint32_t*>(&Bs_lo[nr][cbase]);
                uint32_t bl1 = *reinterpret_cast<const uint32_t*>(&Bs_lo[nr][cbase + 8]);
                #pragma unroll
                for (int mt = 0; mt < 2; mt++) {
                    mma_bf16(c[mt][nt], ah[mt], bh0, bh1);   // hi*hi
                    mma_bf16(c[mt][nt], ah[mt], bl0, bl1);   // hi*lo
                    mma_bf16(c[mt][nt], al[mt], bh0, bh1);   // lo*hi
                }
            }
        }
        __syncthreads();
    }

    // epilogue: + bias, store
    #pragma unroll
    for (int mt = 0; mt < 2; mt++) {
        int m0r = mBase + wm * 32 + mt * 16 + g;
        #pragma unroll
        for (int nt = 0; nt < 6; nt++) {
            int col = wn * 48 + nt * 8 + 2 * tq;
            float b0 = g_bc[col], b1 = g_bc[col + 1];
            float2 v0 = {c[mt][nt][0] + b0, c[mt][nt][1] + b1};
            float2 v1 = {c[mt][nt][2] + b0, c[mt][nt][3] + b1};
            *reinterpret_cast<float2*>(&g_gi[(size_t)m0r * G3 + col]) = v0;
            *reinterpret_cast<float2*>(&g_gi[(size_t)(m0r + 8) * G3 + col]) = v1;
        }
    }
}

// ---------------- GRU: one warp per batch, smem h-broadcast ----------------
__global__ void __launch_bounds__(32) gru_kernel(const float* __restrict__ w_hh,
                                                 const float* __restrict__ b_hh) {
    __shared__ float hbuf[2][32];
    int b = blockIdx.x, lane = threadIdx.x;
    float wr[32], wz[32], wn[32];
    #pragma unroll
    for (int j = 0; j < 32; j++) {
        wr[j] = w_hh[lane * 32 + j];
        wz[j] = w_hh[(32 + lane) * 32 + j];
        wn[j] = w_hh[(64 + lane) * 32 + j];
    }
    float bhr = b_hh[lane], bhz = b_hh[32 + lane], bhn = b_hh[64 + lane];
    const float* gib = g_gi + (size_t)b * T_ * G3;
    float* hsb = g_hs + (size_t)b * T_ * H_;

    hbuf[0][lane] = 0.f;
    __syncwarp();

    // prefetch depth 2 (clamped tail)
    float grA = gib[lane],      gzA = gib[32 + lane],      gnA = gib[64 + lane];
    float grB = gib[G3 + lane], gzB = gib[G3 + 32 + lane], gnB = gib[G3 + 64 + lane];

    for (int t = 0; t < T_; t++) {
        int p = t & 1;
        int tp = (t + 2 < T_) ? (t + 2) : (T_ - 1);
        const float* pf = gib + (size_t)tp * G3;
        float grC = pf[lane], gzC = pf[32 + lane], gnC = pf[64 + lane];

        // broadcast-read all 32 h values (8 x LDS.128, conflict-free)
        float hv[32];
        const float4* hb4 = reinterpret_cast<const float4*>(&hbuf[p][0]);
        #pragma unroll
        for (int i = 0; i < 8; i++) {
            float4 v = hb4[i];
            hv[4 * i] = v.x; hv[4 * i + 1] = v.y;
            hv[4 * i + 2] = v.z; hv[4 * i + 3] = v.w;
        }

        // 12 independent 8-deep FMA chains
        float ar0 = 0.f, ar1 = 0.f, ar2 = 0.f, ar3 = 0.f;
        float az0 = 0.f, az1 = 0.f, az2 = 0.f, az3 = 0.f;
        float an0 = 0.f, an1 = 0.f, an2 = 0.f, an3 = 0.f;
        #pragma unroll
        for (int j = 0; j < 8; j++) {
            ar0 = fmaf(wr[j],      hv[j],      ar0);
            ar1 = fmaf(wr[j + 8],  hv[j + 8],  ar1);
            ar2 = fmaf(wr[j + 16], hv[j + 16], ar2);
            ar3 = fmaf(wr[j + 24], hv[j + 24], ar3);
            az0 = fmaf(wz[j],      hv[j],      az0);
            az1 = fmaf(wz[j + 8],  hv[j + 8],  az1);
            az2 = fmaf(wz[j + 16], hv[j + 16], az2);
            az3 = fmaf(wz[j + 24], hv[j + 24], az3);
            an0 = fmaf(wn[j],      hv[j],      an0);
            an1 = fmaf(wn[j + 8],  hv[j + 8],  an1);
            an2 = fmaf(wn[j + 16], hv[j + 16], an2);
            an3 = fmaf(wn[j + 24], hv[j + 24], an3);
        }
        float ar = (ar0 + ar1) + (ar2 + ar3);
        float az = (az0 + az1) + (az2 + az3);
        float an = (an0 + an1) + (an2 + an3);

        float h = hv[lane];
        float r = sigmoid_fast(grA + ar + bhr);
        float z = sigmoid_fast(gzA + az + bhz);
        float n = tanh_fast(gnA + r * (an + bhn));
        float hn = n + z * (h - n);            // (1-z)*n + z*h
        hbuf[p ^ 1][lane] = hn;
        hsb[t * H_ + lane] = hn;
        grA = grB; gzA = gzB; gnA = gnB;
        grB = grC; gzB = gzC; gnB = gnC;
        __syncwarp();
    }
}

// ---------------- post: q, windows, masked mean, output head ----------------
__global__ void __launch_bounds__(128) post_kernel(
        const int* __restrict__ x_len,
        const float* __restrict__ w_reg, const float* __restrict__ b_reg,
        const float* __restrict__ wn1, const float* __restrict__ bn1,
        const float* __restrict__ wn2, const float* __restrict__ bn2,
        const float* __restrict__ wlm, const float* __restrict__ blm,
        float* __restrict__ out, int out_size) {
    __shared__ float sq[T_];
    __shared__ float red[128];
    __shared__ float swr[32];
    int b = blockIdx.x, tid = threadIdx.x;
    int len = x_len[b];
    if (tid < 32) swr[tid] = w_reg[tid];
    __syncthreads();
    float br = b_reg[0];
    const float* hsb = g_hs + (size_t)b * T_ * H_;

    for (int t = tid; t < T_; t += 128) {
        const float* hp = hsb + t * H_;
        float acc = 0.f;
        #pragma unroll
        for (int j = 0; j < 32; j++) acc = fmaf(hp[j], swr[j], acc);
        sq[t] = acc + br;
    }
    __syncthreads();

    float sum = 0.f;
    for (int t = tid; t < T_; t += 128) {
        if (t < len) {
            float l = sq[t];
            #pragma unroll
            for (int k = 1; k < TAU; k++) {
                int i = t - k;
                if (i >= 0) l = fminf(l, sq[i]);
            }
            float num = 0.f, den = 0.f;
            #pragma unroll
            for (int k = 0; k < TAU; k++) {
                int i = t + k;
                float v = (i < len) ? sq[i] : QPV;
                float e = __expf(-v);
                num = fmaf(v, e, num);
                den += e;
            }
            float m = num / den;
            sum += 0.5f * m + 0.5f * l;
        }
    }
    red[tid] = sum;
    __syncthreads();
    for (int s = 64; s > 0; s >>= 1) {
        if (tid < s) red[tid] += red[tid + s];
        __syncthreads();
    }
    if (tid == 0) {
        float rel      = red[0] / (float)len;
        float relative = 1.f / (1.f + expf(-rel));
        float mapped   = wn2[0] * (1.f / (1.f + expf(-(relative * wn1[0] + bn1[0])))) + bn2[0];
        float aligned  = mapped * wlm[0] + blm[0];
        if (out_size >= 3 * B_) {
            out[b] = relative; out[B_ + b] = mapped; out[2 * B_ + b] = aligned;
        } else {
            out[b] = aligned;
        }
    }
}

// ---------------- launch ----------------
extern "C" void kernel_launch(void* const* d_in, const int* in_sizes, int n_in,
                              void* d_out, int out_size) {
    const float* x     = (const float*)d_in[0];
    const int*   xlen  = (const int*)  d_in[1];
    const float* w_dr  = (const float*)d_in[2];
    const float* b_dr  = (const float*)d_in[3];
    const float* w_ih  = (const float*)d_in[4];
    const float* w_hh  = (const float*)d_in[5];
    const float* b_ih  = (const float*)d_in[6];
    const float* b_hh  = (const float*)d_in[7];
    const float* w_reg = (const float*)d_in[8];
    const float* b_reg = (const float*)d_in[9];
    const float* wn1   = (const float*)d_in[10];
    const float* bn1   = (const float*)d_in[11];
    const float* wn2   = (const float*)d_in[12];
    const float* bn2   = (const float*)d_in[13];
    const float* wlm   = (const float*)d_in[14];
    const float* blm   = (const float*)d_in[15];

    prep_wc<<<DIN / 128, 128>>>(w_ih, w_dr);
    prep_bc<<<1, G3>>>(w_ih, b_dr, b_ih);
    gemm_gi<<<(B_ * T_) / GBM, 256>>>(x);
    gru_kernel<<<B_, 32>>>(w_hh, b_hh);
    post_kernel<<<B_, 128>>>(xlen, w_reg, b_reg, wn1, bn1, wn2, bn2, wlm, blm,
                             (float*)d_out, out_size);
}

// round 7
// speedup vs baseline: 1.5305x; 1.0114x over previous
#include <cuda_runtime.h>
#include <cuda_bf16.h>
#include <cstdint>

#define B_   16
#define T_   1024
#define DIN  4608
#define DRED 128
#define H_   32
#define G3   96          // 3*H
#define TAU  12
#define QPV  1e4f

// ---------------- scratch (no cudaMalloc allowed) ----------------
__device__ __nv_bfloat16 g_wc_hi[G3 * DIN];  // folded weight, bf16 hi part
__device__ __nv_bfloat16 g_wc_lo[G3 * DIN];  // folded weight, bf16 lo part
__device__ float g_bc[G3];                   // folded bias b_ih + w_ih@b_dr
__device__ float g_gi[B_ * T_ * G3];         // input-gate preactivations
__device__ float g_hs[B_ * T_ * H_];         // GRU hidden states

__device__ __forceinline__ float sigmoid_fast(float x) {
    return __fdividef(1.f, 1.f + __expf(-x));
}
__device__ __forceinline__ float tanh_fast(float x) {
    return 2.f * __fdividef(1.f, 1.f + __expf(-2.f * x)) - 1.f;
}

// ---------------- prep: fold the two linear layers ----------------
__global__ void prep_bc(const float* __restrict__ w_ih,
                        const float* __restrict__ b_dr,
                        const float* __restrict__ b_ih) {
    int o = threadIdx.x;              // 96 threads
    float acc = b_ih[o];
    #pragma unroll 8
    for (int r = 0; r < DRED; r++) acc = fmaf(w_ih[o * DRED + r], b_dr[r], acc);
    g_bc[o] = acc;
}

// w_c[o][d] = sum_r w_ih[o][r] * w_dr[r][d]; split into bf16 hi/lo
__global__ void __launch_bounds__(128) prep_wc(const float* __restrict__ w_ih,
                                               const float* __restrict__ w_dr) {
    int tid = threadIdx.x;
    int d = blockIdx.x * 128 + tid;   // 36 blocks * 128 = 4608 columns
    float acc[G3];
    #pragma unroll
    for (int o = 0; o < G3; o++) acc[o] = 0.f;
    for (int r = 0; r < DRED; r++) {
        float a = w_dr[(size_t)r * DIN + d];
        #pragma unroll
        for (int o = 0; o < G3; o++)
            acc[o] = fmaf(__ldg(&w_ih[o * DRED + r]), a, acc[o]);
    }
    #pragma unroll
    for (int o = 0; o < G3; o++) {
        float v = acc[o];
        __nv_bfloat16 hi = __float2bfloat16(v);
        __nv_bfloat16 lo = __float2bfloat16(v - __bfloat162float(hi));
        g_wc_hi[(size_t)o * DIN + d] = hi;
        g_wc_lo[(size_t)o * DIN + d] = lo;
    }
}

// ---------------- big GEMM: gi = x @ w_c.T + b_c  (bf16x3 HMMA) ----------------
// M=16384, N=96, K=4608.  Block tile 128x96xBK32, 8 warps (4x2), warp 32x48.
#define GBM 128
#define GBN 96
#define GBK 32
#define APAD 40   // bf16 elems per smem row (80 B, conflict-spread)

__device__ __forceinline__ void mma_bf16(float c[4], const uint32_t a[4],
                                         uint32_t b0, uint32_t b1) {
    asm volatile(
        "mma.sync.aligned.m16n8k16.row.col.f32.bf16.bf16.f32 "
        "{%0,%1,%2,%3}, {%4,%5,%6,%7}, {%8,%9}, {%0,%1,%2,%3};\n"
        : "+f"(c[0]), "+f"(c[1]), "+f"(c[2]), "+f"(c[3])
        : "r"(a[0]), "r"(a[1]), "r"(a[2]), "r"(a[3]), "r"(b0), "r"(b1));
}

__global__ void __launch_bounds__(256) gemm_gi(const float* __restrict__ x) {
    __shared__ __nv_bfloat16 As_hi[GBM][APAD], As_lo[GBM][APAD];  // 20 KB
    __shared__ __nv_bfloat16 Bs_hi[GBN][APAD], Bs_lo[GBN][APAD];  // 15 KB
    int tid = threadIdx.x;
    int wid = tid >> 5, lane = tid & 31;
    int wm = wid & 3, wn = wid >> 2;          // 4 x 2 warp grid
    int g = lane >> 2, tq = lane & 3;         // fragment row-group / quad
    int mBase = blockIdx.x * GBM;

    float c[2][6][4];
    #pragma unroll
    for (int mt = 0; mt < 2; mt++)
        #pragma unroll
        for (int nt = 0; nt < 6; nt++)
            #pragma unroll
            for (int i = 0; i < 4; i++) c[mt][nt][i] = 0.f;

    for (int kb = 0; kb < DIN; kb += GBK) {
        // --- A tile: 128x32 fp32 -> bf16 hi/lo in smem ---
        #pragma unroll
        for (int i = 0; i < 4; i++) {
            int idx = tid + i * 256;           // 0..1023
            int row = idx >> 3, kq = idx & 7;  // cols 4kq..4kq+3
            float4 v = *reinterpret_cast<const float4*>(
                x + (size_t)(mBase + row) * DIN + kb + 4 * kq);
            __nv_bfloat16 h0 = __float2bfloat16(v.x);
            __nv_bfloat16 h1 = __float2bfloat16(v.y);
            __nv_bfloat16 h2 = __float2bfloat16(v.z);
            __nv_bfloat16 h3 = __float2bfloat16(v.w);
            __nv_bfloat16 l0 = __float2bfloat16(v.x - __bfloat162float(h0));
            __nv_bfloat16 l1 = __float2bfloat16(v.y - __bfloat162float(h1));
            __nv_bfloat16 l2 = __float2bfloat16(v.z - __bfloat162float(h2));
            __nv_bfloat16 l3 = __float2bfloat16(v.w - __bfloat162float(h3));
            *reinterpret_cast<__nv_bfloat162*>(&As_hi[row][4 * kq])     = {h0, h1};
            *reinterpret_cast<__nv_bfloat162*>(&As_hi[row][4 * kq + 2]) = {h2, h3};
            *reinterpret_cast<__nv_bfloat162*>(&As_lo[row][4 * kq])     = {l0, l1};
            *reinterpret_cast<__nv_bfloat162*>(&As_lo[row][4 * kq + 2]) = {l2, l3};
        }
        // --- B tile: 96x32 bf16 hi/lo ---
        #pragma unroll
        for (int i = 0; i < 6; i++) {
            int idx = tid + i * 256;            // 0..1535
            int n = idx >> 4, kq = idx & 15;    // bf16 cols 2kq..2kq+1
            *reinterpret_cast<__nv_bfloat162*>(&Bs_hi[n][2 * kq]) =
                *reinterpret_cast<const __nv_bfloat162*>(&g_wc_hi[(size_t)n * DIN + kb + 2 * kq]);
            *reinterpret_cast<__nv_bfloat162*>(&Bs_lo[n][2 * kq]) =
                *reinterpret_cast<const __nv_bfloat162*>(&g_wc_lo[(size_t)n * DIN + kb + 2 * kq]);
        }
        __syncthreads();

        #pragma unroll
        for (int ks = 0; ks < 2; ks++) {
            uint32_t ah[2][4], al[2][4];
            #pragma unroll
            for (int mt = 0; mt < 2; mt++) {
                int r = wm * 32 + mt * 16 + g;
                int cbase = ks * 16 + 2 * tq;
                ah[mt][0] = *reinterpret_cast<const uint32_t*>(&As_hi[r][cbase]);
                ah[mt][1] = *reinterpret_cast<const uint32_t*>(&As_hi[r + 8][cbase]);
                ah[mt][2] = *reinterpret_cast<const uint32_t*>(&As_hi[r][cbase + 8]);
                ah[mt][3] = *reinterpret_cast<const uint32_t*>(&As_hi[r + 8][cbase + 8]);
                al[mt][0] = *reinterpret_cast<const uint32_t*>(&As_lo[r][cbase]);
                al[mt][1] = *reinterpret_cast<const uint32_t*>(&As_lo[r + 8][cbase]);
                al[mt][2] = *reinterpret_cast<const uint32_t*>(&As_lo[r][cbase + 8]);
                al[mt][3] = *reinterpret_cast<const uint32_t*>(&As_lo[r + 8][cbase + 8]);
            }
            #pragma unroll
            for (int nt = 0; nt < 6; nt++) {
                int nr = wn * 48 + nt * 8 + g;
                int cbase = ks * 16 + 2 * tq;
                uint32_t bh0 = *reinterpret_cast<const uint32_t*>(&Bs_hi[nr][cbase]);
                uint32_t bh1 = *reinterpret_cast<const uint32_t*>(&Bs_hi[nr][cbase + 8]);
                uint32_t bl0 = *reinterpret_cast<const uint32_t*>(&Bs_lo[nr][cbase]);
                uint32_t bl1 = *reinterpret_cast<const uint32_t*>(&Bs_lo[nr][cbase + 8]);
                #pragma unroll
                for (int mt = 0; mt < 2; mt++) {
                    mma_bf16(c[mt][nt], ah[mt], bh0, bh1);   // hi*hi
                    mma_bf16(c[mt][nt], ah[mt], bl0, bl1);   // hi*lo
                    mma_bf16(c[mt][nt], al[mt], bh0, bh1);   // lo*hi
                }
            }
        }
        __syncthreads();
    }

    // epilogue: + bias, store
    #pragma unroll
    for (int mt = 0; mt < 2; mt++) {
        int m0r = mBase + wm * 32 + mt * 16 + g;
        #pragma unroll
        for (int nt = 0; nt < 6; nt++) {
            int col = wn * 48 + nt * 8 + 2 * tq;
            float b0 = g_bc[col], b1 = g_bc[col + 1];
            float2 v0 = {c[mt][nt][0] + b0, c[mt][nt][1] + b1};
            float2 v1 = {c[mt][nt][2] + b0, c[mt][nt][3] + b1};
            *reinterpret_cast<float2*>(&g_gi[(size_t)m0r * G3 + col]) = v0;
            *reinterpret_cast<float2*>(&g_gi[(size_t)(m0r + 8) * G3 + col]) = v1;
        }
    }
}

// ---------------- GRU: one warp per batch, smem h-broadcast ----------------
// Key fix vs R4: lane's own h is carried in a scalar register (no hv[lane]
// dynamic index -> no local-memory demotion / LDL traffic).
__global__ void __launch_bounds__(32) gru_kernel(const float* __restrict__ w_hh,
                                                 const float* __restrict__ b_hh) {
    __shared__ __align__(16) float hbuf[2][32];
    int b = blockIdx.x, lane = threadIdx.x;
    float wr[32], wz[32], wn[32];
    #pragma unroll
    for (int j = 0; j < 32; j++) {
        wr[j] = w_hh[lane * 32 + j];
        wz[j] = w_hh[(32 + lane) * 32 + j];
        wn[j] = w_hh[(64 + lane) * 32 + j];
    }
    float bhr = b_hh[lane], bhz = b_hh[32 + lane], bhn = b_hh[64 + lane];
    const float* gib = g_gi + (size_t)b * T_ * G3;
    float* hsb = g_hs + (size_t)b * T_ * H_;

    hbuf[0][lane] = 0.f;
    __syncwarp();

    // prefetch depth 2 (clamped tail)
    float grA = gib[lane],      gzA = gib[32 + lane],      gnA = gib[64 + lane];
    float grB = gib[G3 + lane], gzB = gib[G3 + 32 + lane], gnB = gib[G3 + 64 + lane];

    float h = 0.f;   // this lane's own h, carried in a register

    for (int t = 0; t < T_; t++) {
        int p = t & 1;
        int tp = (t + 2 < T_) ? (t + 2) : (T_ - 1);
        const float* pf = gib + (size_t)tp * G3;
        float grC = pf[lane], gzC = pf[32 + lane], gnC = pf[64 + lane];

        // broadcast-read all 32 h values (8 x LDS.128, static indices only)
        float hv[32];
        const float4* hb4 = reinterpret_cast<const float4*>(&hbuf[p][0]);
        #pragma unroll
        for (int i = 0; i < 8; i++) {
            float4 v = hb4[i];
            hv[4 * i] = v.x; hv[4 * i + 1] = v.y;
            hv[4 * i + 2] = v.z; hv[4 * i + 3] = v.w;
        }

        // 12 independent 8-deep FMA chains
        float ar0 = 0.f, ar1 = 0.f, ar2 = 0.f, ar3 = 0.f;
        float az0 = 0.f, az1 = 0.f, az2 = 0.f, az3 = 0.f;
        float an0 = 0.f, an1 = 0.f, an2 = 0.f, an3 = 0.f;
        #pragma unroll
        for (int j = 0; j < 8; j++) {
            ar0 = fmaf(wr[j],      hv[j],      ar0);
            ar1 = fmaf(wr[j + 8],  hv[j + 8],  ar1);
            ar2 = fmaf(wr[j + 16], hv[j + 16], ar2);
            ar3 = fmaf(wr[j + 24], hv[j + 24], ar3);
            az0 = fmaf(wz[j],      hv[j],      az0);
            az1 = fmaf(wz[j + 8],  hv[j + 8],  az1);
            az2 = fmaf(wz[j + 16], hv[j + 16], az2);
            az3 = fmaf(wz[j + 24], hv[j + 24], az3);
            an0 = fmaf(wn[j],      hv[j],      an0);
            an1 = fmaf(wn[j + 8],  hv[j + 8],  an1);
            an2 = fmaf(wn[j + 16], hv[j + 16], an2);
            an3 = fmaf(wn[j + 24], hv[j + 24], an3);
        }
        float ar = (ar0 + ar1) + (ar2 + ar3);
        float az = (az0 + az1) + (az2 + az3);
        float an = (an0 + an1) + (an2 + an3);

        float r = sigmoid_fast(grA + ar + bhr);
        float z = sigmoid_fast(gzA + az + bhz);
        float n = tanh_fast(gnA + r * (an + bhn));
        float hn = n + z * (h - n);            // (1-z)*n + z*h
        hbuf[p ^ 1][lane] = hn;
        hsb[t * H_ + lane] = hn;
        h = hn;
        grA = grB; gzA = gzB; gnA = gnB;
        grB = grC; gzB = gzC; gnB = gnC;
        __syncwarp();
    }
}

// ---------------- post: q, windows, masked mean, output head ----------------
__global__ void __launch_bounds__(128) post_kernel(
        const int* __restrict__ x_len,
        const float* __restrict__ w_reg, const float* __restrict__ b_reg,
        const float* __restrict__ wn1, const float* __restrict__ bn1,
        const float* __restrict__ wn2, const float* __restrict__ bn2,
        const float* __restrict__ wlm, const float* __restrict__ blm,
        float* __restrict__ out, int out_size) {
    __shared__ float sq[T_];
    __shared__ float red[128];
    __shared__ float swr[32];
    int b = blockIdx.x, tid = threadIdx.x;
    int len = x_len[b];
    if (tid < 32) swr[tid] = w_reg[tid];
    __syncthreads();
    float br = b_reg[0];
    const float* hsb = g_hs + (size_t)b * T_ * H_;

    for (int t = tid; t < T_; t += 128) {
        const float* hp = hsb + t * H_;
        float acc = 0.f;
        #pragma unroll
        for (int j = 0; j < 32; j++) acc = fmaf(hp[j], swr[j], acc);
        sq[t] = acc + br;
    }
    __syncthreads();

    float sum = 0.f;
    for (int t = tid; t < T_; t += 128) {
        if (t < len) {
            float l = sq[t];
            #pragma unroll
            for (int k = 1; k < TAU; k++) {
                int i = t - k;
                if (i >= 0) l = fminf(l, sq[i]);
            }
            float num = 0.f, den = 0.f;
            #pragma unroll
            for (int k = 0; k < TAU; k++) {
                int i = t + k;
                float v = (i < len) ? sq[i] : QPV;
                float e = __expf(-v);
                num = fmaf(v, e, num);
                den += e;
            }
            float m = num / den;
            sum += 0.5f * m + 0.5f * l;
        }
    }
    red[tid] = sum;
    __syncthreads();
    for (int s = 64; s > 0; s >>= 1) {
        if (tid < s) red[tid] += red[tid + s];
        __syncthreads();
    }
    if (tid == 0) {
        float rel      = red[0] / (float)len;
        float relative = 1.f / (1.f + expf(-rel));
        float mapped   = wn2[0] * (1.f / (1.f + expf(-(relative * wn1[0] + bn1[0])))) + bn2[0];
        float aligned  = mapped * wlm[0] + blm[0];
        if (out_size >= 3 * B_) {
            out[b] = relative; out[B_ + b] = mapped; out[2 * B_ + b] = aligned;
        } else {
            out[b] = aligned;
        }
    }
}

// ---------------- launch ----------------
extern "C" void kernel_launch(void* const* d_in, const int* in_sizes, int n_in,
                              void* d_out, int out_size) {
    const float* x     = (const float*)d_in[0];
    const int*   xlen  = (const int*)  d_in[1];
    const float* w_dr  = (const float*)d_in[2];
    const float* b_dr  = (const float*)d_in[3];
    const float* w_ih  = (const float*)d_in[4];
    const float* w_hh  = (const float*)d_in[5];
    const float* b_ih  = (const float*)d_in[6];
    const float* b_hh  = (const float*)d_in[7];
    const float* w_reg = (const float*)d_in[8];
    const float* b_reg = (const float*)d_in[9];
    const float* wn1   = (const float*)d_in[10];
    const float* bn1   = (const float*)d_in[11];
    const float* wn2   = (const float*)d_in[12];
    const float* bn2   = (const float*)d_in[13];
    const float* wlm   = (const float*)d_in[14];
    const float* blm   = (const float*)d_in[15];

    prep_wc<<<DIN / 128, 128>>>(w_ih, w_dr);
    prep_bc<<<1, G3>>>(w_ih, b_dr, b_ih);
    gemm_gi<<<(B_ * T_) / GBM, 256>>>(x);
    gru_kernel<<<B_, 32>>>(w_hh, b_hh);
    post_kernel<<<B_, 128>>>(xlen, w_reg, b_reg, wn1, bn1, wn2, bn2, wlm, blm,
                             (float*)d_out, out_size);
}